// round 5
// baseline (speedup 1.0000x reference)
#include <cuda_runtime.h>
#include <math.h>

#define HH 112
#define WW 112
#define NPIX (HH*WW)          // 12544
#define GRID 7
#define NCELL 49
#define NFEAT 1822
#define BMAX 1024
#define TWO_PI_F 6.283185307179586f

// ---- scratch (static device arrays; no cudaMalloc anywhere) ----
__device__ float d_gray[(size_t)BMAX * NPIX];
__device__ float d_tmp0[(size_t)BMAX * NPIX];
__device__ float d_tmp1[(size_t)BMAX * NPIX];
__device__ float d_part[(size_t)BMAX * NCELL * 9];

// =====================================================================
// Kernel 1: per-cell features (hist, HSV, Sobel, Laplacian) + gray out
// block = (16,16) threads, grid = (49, B)
// Interior gray comes from the per-pixel RGB reads (no tile re-read);
// only the 68 perimeter halo positions do extra global loads.
// =====================================================================
__global__ void __launch_bounds__(256) cell_kernel(const float* __restrict__ img,
                                                   float* __restrict__ out)
{
    const int cell = blockIdx.x;
    const int b    = blockIdx.y;
    const int cy = cell / GRID, cx = cell % GRID;
    const int tx = threadIdx.x, ty = threadIdx.y;
    const int tid = ty * 16 + tx;

    __shared__ float sg[18][18];
    __shared__ int   shist[24];
    __shared__ float sred[15][8];
    __shared__ float stot[15];

    if (tid < 24) shist[tid] = 0;

    const float* base = img + (size_t)b * 3 * NPIX;
    const int oy = cy * 16 - 1;
    const int ox = cx * 16 - 1;

    const int gy = cy * 16 + ty;
    const int gx = cx * 16 + tx;
    const int p = gy * WW + gx;
    const float r  = base[p];
    const float g  = base[NPIX + p];
    const float bl = base[2 * NPIX + p];
    const float gray = 0.299f * r + 0.587f * g + 0.114f * bl;
    sg[ty + 1][tx + 1] = gray;

    // halo: 68 perimeter positions of the 18x18 tile, coords clamped
    if (tid < 68) {
        int rr, cc;
        if (tid < 18)      { rr = 0;            cc = tid; }
        else if (tid < 36) { rr = 17;           cc = tid - 18; }
        else if (tid < 52) { rr = tid - 36 + 1; cc = 0; }
        else               { rr = tid - 52 + 1; cc = 17; }
        int yy = min(max(oy + rr, 0), HH - 1);
        int xx = min(max(ox + cc, 0), WW - 1);
        int pp = yy * WW + xx;
        sg[rr][cc] = 0.299f * base[pp] + 0.587f * base[NPIX + pp] + 0.114f * base[2 * NPIX + pp];
    }
    __syncthreads();

    // --- histogram ---
    int ir = (int)floorf(r  * 8.0f); if (ir >= 0 && ir < 8) atomicAdd(&shist[ir], 1);
    int ig = (int)floorf(g  * 8.0f); if (ig >= 0 && ig < 8) atomicAdd(&shist[8 + ig], 1);
    int ib = (int)floorf(bl * 8.0f); if (ib >= 0 && ib < 8) atomicAdd(&shist[16 + ib], 1);

    // --- HSV (matches reference branch order exactly) ---
    float maxc = fmaxf(r, fmaxf(g, bl));
    float minc = fminf(r, fminf(g, bl));
    float vv = maxc;
    float delta = maxc - minc;
    float ss = delta / (maxc + 1e-8f);
    float dsafe = (delta == 0.0f) ? 1.0f : delta;
    float rc = (maxc - r)  / dsafe;
    float gc = (maxc - g)  / dsafe;
    float bc = (maxc - bl) / dsafe;
    float hh;
    if (maxc == r)      hh = bc - gc;
    else if (maxc == g) hh = 2.0f + rc - bc;
    else                hh = 4.0f + gc - rc;
    hh = hh / 6.0f;
    hh = hh - floorf(hh);
    hh = hh * TWO_PI_F;

    // write gray pixel for the Gabor passes
    d_gray[(size_t)b * NPIX + p] = gray;

    // --- Sobel (edge/clamp padding) ---
    const int y0 = gy - oy, x0 = gx - ox;               // = ty+1, tx+1
    const int ym = min(max(gy - 1, 0), HH - 1) - oy;
    const int yp = min(max(gy + 1, 0), HH - 1) - oy;
    const int xm = min(max(gx - 1, 0), WW - 1) - ox;
    const int xp = min(max(gx + 1, 0), WW - 1) - ox;
    float gxv = 0.125f * ((sg[ym][xp] + 2.0f * sg[y0][xp] + sg[yp][xp])
                        - (sg[ym][xm] + 2.0f * sg[y0][xm] + sg[yp][xm]));
    float gyv = 0.125f * ((sg[yp][xm] + 2.0f * sg[yp][x0] + sg[yp][xp])
                        - (sg[ym][xm] + 2.0f * sg[ym][x0] + sg[ym][xp]));
    float mag = sqrtf(gxv * gxv + gyv * gyv + 1e-8f);
    float d2  = gxv * gxv + gyv * gyv;
    float ca  = (d2 > 0.0f) ? gxv * rsqrtf(d2) : 1.0f;  // cos(atan2(gy,gx))

    // --- Laplacian (reflect padding) ---
    const int Rym = ((gy - 1) < 0      ? 1      : (gy - 1)) - oy;
    const int Ryp = ((gy + 1) > HH - 1 ? HH - 2 : (gy + 1)) - oy;
    const int Rxm = ((gx - 1) < 0      ? 1      : (gx - 1)) - ox;
    const int Rxp = ((gx + 1) > WW - 1 ? WW - 2 : (gx + 1)) - ox;
    float nb = sg[Rym][Rxm] + sg[Rym][x0] + sg[Rym][Rxp]
             + sg[y0][Rxm]               + sg[y0][Rxp]
             + sg[Ryp][Rxm] + sg[Ryp][x0] + sg[Ryp][Rxp];
    float lap = 0.0625f * nb - 0.5f * sg[y0][x0];

    // --- 15 block reductions ---
    float vals[15];
    vals[0] = r;  vals[1] = g;  vals[2] = bl;
    vals[3] = hh; vals[4] = ss; vals[5] = vv;
    vals[6] = hh * hh; vals[7] = ss * ss; vals[8] = vv * vv;
    vals[9] = mag; vals[10] = mag * mag; vals[11] = ca;
    vals[12] = lap; vals[13] = lap * lap; vals[14] = fabsf(lap);

    const int lane = tid & 31, w = tid >> 5;
    #pragma unroll
    for (int k = 0; k < 15; k++) {
        float x = vals[k];
        #pragma unroll
        for (int o = 16; o > 0; o >>= 1) x += __shfl_down_sync(0xffffffffu, x, o);
        if (lane == 0) sred[k][w] = x;
    }
    __syncthreads();
    if (tid < 15) {
        float x = 0.0f;
        #pragma unroll
        for (int ww = 0; ww < 8; ww++) x += sred[tid][ww];
        stot[tid] = x;
    }
    __syncthreads();

    float* ob = out + (size_t)b * NFEAT;
    // hist features: layout (gy,gx,channel,bin)
    if (tid < 24) {
        int c = tid >> 3, bin = tid & 7;
        ob[3 + ((size_t)cell * 3 + c) * 8 + bin] = (float)shist[tid] * (1.0f / 256.0f);
    }
    // hsv grid means (gy,gx,channel)
    if (tid < 3) ob[1185 + cell * 3 + tid] = stot[3 + tid] * (1.0f / 256.0f);
    // per-image partials (rgb sums, hsv sums, hsv sq-sums)
    if (tid < 9) d_part[((size_t)b * NCELL + cell) * 9 + tid] = stot[tid];
    if (tid == 0) {
        float sm = stot[9], sq = stot[10];
        ob[1332 + cell * 4 + 0] = sm * (1.0f / 256.0f);
        ob[1332 + cell * 4 + 1] = sqrtf(fmaxf(0.0f, (sq - sm * sm * (1.0f / 256.0f)) * (1.0f / 255.0f)));
        ob[1332 + cell * 4 + 2] = sq * (1.0f / 256.0f);
        ob[1332 + cell * 4 + 3] = stot[11] * (1.0f / 256.0f);
        float lm = stot[12], lq = stot[13];
        ob[1528 + cell * 4 + 0] = lm * (1.0f / 256.0f);
        ob[1528 + cell * 4 + 1] = sqrtf(fmaxf(0.0f, (lq - lm * lm * (1.0f / 256.0f)) * (1.0f / 255.0f)));
        ob[1528 + cell * 4 + 2] = lq * (1.0f / 256.0f);
        ob[1528 + cell * 4 + 3] = stot[14] * (1.0f / 256.0f);
    }
}

// =====================================================================
// Kernel 2: horizontal separable Gabor pass, both orientations fused.
// Rank-1 factors: horizontal factor = center row of the 21x21 kernel.
// block = 128 threads = 16 x-threads x 8 rows; each thread computes 7
// consecutive outputs (27 smem loads -> 294 FMAs; taps in registers).
// grid = B*112/8 blocks (rows are always a multiple of 8).
// =====================================================================
__global__ void __launch_bounds__(128) gabor_h(const float* __restrict__ gk0,
                                               const float* __restrict__ gk1)
{
    __shared__ float srow[8][132];
    const int tid = threadIdx.x;
    const int txi = tid & 15;           // 16 x-threads, 7 outputs each
    const int ry  = tid >> 4;           // 8 rows per block
    const int row0 = blockIdx.x * 8;

    float f0[21], f1[21];
    #pragma unroll
    for (int d = 0; d < 21; d++) {
        f0[d] = __ldg(&gk0[210 + d]);
        f1[d] = __ldg(&gk1[210 + d]);
    }

    // load 8 rows x (112 + 2*10 halo), zero padded horizontally
    for (int i = tid; i < 8 * 132; i += 128) {
        int rr = i / 132, cc = i % 132;
        int xx = cc - 10;
        srow[rr][cc] = (xx >= 0 && xx < WW)
                     ? d_gray[(size_t)(row0 + rr) * WW + xx] : 0.0f;
    }
    __syncthreads();

    const int x0 = txi * 7;   // padded index: output x uses srow[x .. x+20]
    float a0[7], a1[7];
    #pragma unroll
    for (int i = 0; i < 7; i++) { a0[i] = 0.0f; a1[i] = 0.0f; }

    #pragma unroll
    for (int k = 0; k < 27; k++) {
        float v = srow[ry][x0 + k];
        #pragma unroll
        for (int i = 0; i < 7; i++) {
            int d = k - i;
            if (d >= 0 && d < 21) {
                a0[i] = fmaf(f0[d], v, a0[i]);
                a1[i] = fmaf(f1[d], v, a1[i]);
            }
        }
    }

    size_t o = (size_t)(row0 + ry) * WW + x0;
    #pragma unroll
    for (int i = 0; i < 7; i++) {
        d_tmp0[o + i] = a0[i];
        d_tmp1[o + i] = a1[i];
    }
}

// =====================================================================
// Kernel 3: vertical Gabor pass + |.| + per-cell means.
// Vertical factor = center column / center element (rank-1 norm fold).
// block = 224 threads = 16 cols x 14 y-threads; each thread computes 8
// consecutive y outputs (2x28 smem loads -> 336 FMAs). Warp w == cell
// row w, so the cell mean is one warp reduction.
// grid = (7 col-strips, B). Row stride 18 => conflict-free banks.
// =====================================================================
__global__ void __launch_bounds__(224) gabor_v(const float* __restrict__ gk0,
                                               const float* __restrict__ gk1,
                                               float* __restrict__ out)
{
    __shared__ float s0[132][18];
    __shared__ float s1[132][18];

    const int b  = blockIdx.y;
    const int cx = blockIdx.x;
    const int tid = threadIdx.x;
    const int txi = tid & 15;
    const int ty  = tid >> 4;           // 0..13

    float g0[21], g1[21];
    {
        float inv0 = 1.0f / __ldg(&gk0[220]);
        float inv1 = 1.0f / __ldg(&gk1[220]);
        #pragma unroll
        for (int d = 0; d < 21; d++) {
            g0[d] = __ldg(&gk0[d * 21 + 10]) * inv0;
            g1[d] = __ldg(&gk1[d * 21 + 10]) * inv1;
        }
    }

    const int x0 = cx * 16;
    const float* t0 = d_tmp0 + (size_t)b * NPIX;
    const float* t1 = d_tmp1 + (size_t)b * NPIX;
    for (int i = tid; i < 132 * 16; i += 224) {
        int rr = i >> 4, cc = i & 15;
        int yy = rr - 10;
        bool in = (yy >= 0 && yy < HH);
        s0[rr][cc] = in ? t0[yy * WW + x0 + cc] : 0.0f;
        s1[rr][cc] = in ? t1[yy * WW + x0 + cc] : 0.0f;
    }
    __syncthreads();

    const int ybase = ty * 8;   // outputs y = ybase..ybase+7; padded rows ybase+k
    float a0[8], a1[8];
    #pragma unroll
    for (int j = 0; j < 8; j++) { a0[j] = 0.0f; a1[j] = 0.0f; }

    #pragma unroll
    for (int k = 0; k < 28; k++) {
        float v0 = s0[ybase + k][txi];
        float v1 = s1[ybase + k][txi];
        #pragma unroll
        for (int j = 0; j < 8; j++) {
            int d = k - j;
            if (d >= 0 && d < 21) {
                a0[j] = fmaf(g0[d], v0, a0[j]);
                a1[j] = fmaf(g1[d], v1, a1[j]);
            }
        }
    }

    float sum0 = 0.0f, sum1 = 0.0f;
    #pragma unroll
    for (int j = 0; j < 8; j++) { sum0 += fabsf(a0[j]); sum1 += fabsf(a1[j]); }

    #pragma unroll
    for (int o = 16; o > 0; o >>= 1) {
        sum0 += __shfl_down_sync(0xffffffffu, sum0, o);
        sum1 += __shfl_down_sync(0xffffffffu, sum1, o);
    }
    if ((tid & 31) == 0) {
        int w = tid >> 5;               // warp id == cell row
        float* ob = out + (size_t)b * NFEAT;
        ob[1724 + w * GRID + cx] = sum0 * (1.0f / 256.0f);
        ob[1773 + w * GRID + cx] = sum1 * (1.0f / 256.0f);
    }
}

// =====================================================================
// Kernel 4: per-image finalize (channel means, HSV mean/std ddof=1)
// =====================================================================
__global__ void finalize(float* __restrict__ out)
{
    __shared__ float sums[9];
    const int b = blockIdx.x;
    const int t = threadIdx.x;
    if (t < 9) {
        float a = 0.0f;
        const float* pp = d_part + (size_t)b * NCELL * 9;
        for (int c = 0; c < NCELL; c++) a += pp[c * 9 + t];
        sums[t] = a;
    }
    __syncthreads();
    if (t == 0) {
        float* ob = out + (size_t)b * NFEAT;
        const float N = (float)NPIX;
        ob[0] = sums[0] / N;
        ob[1] = sums[1] / N;
        ob[2] = sums[2] / N;
        #pragma unroll
        for (int k = 0; k < 3; k++) {
            float sm = sums[3 + k];
            float sq = sums[6 + k];
            float var = (sq - sm * sm / N) / (N - 1.0f);
            ob[1179 + 2 * k] = sm / N;
            ob[1180 + 2 * k] = sqrtf(fmaxf(var, 0.0f));
        }
    }
}

// =====================================================================
extern "C" void kernel_launch(void* const* d_in, const int* in_sizes, int n_in,
                              void* d_out, int out_size)
{
    const float* img = (const float*)d_in[0];
    const float* gk0 = (const float*)d_in[1];
    const float* gk1 = (const float*)d_in[2];
    float* out = (float*)d_out;

    int B = in_sizes[0] / (3 * NPIX);
    if (B > BMAX) B = BMAX;

    cell_kernel<<<dim3(NCELL, B), dim3(16, 16)>>>(img, out);

    gabor_h<<<B * (HH / 8), 128>>>(gk0, gk1);

    gabor_v<<<dim3(GRID, B), 224>>>(gk0, gk1, out);

    finalize<<<B, 32>>>(out);
}

// round 6
// speedup vs baseline: 1.6355x; 1.6355x over previous
#include <cuda_runtime.h>
#include <math.h>

#define HH 112
#define WW 112
#define NPIX (HH*WW)          // 12544
#define GRID 7
#define NCELL 49
#define NFEAT 1822
#define BMAX 1024
#define TWO_PI_F 6.283185307179586f

// ---- scratch (static device arrays; no cudaMalloc anywhere) ----
__device__ float d_gray[(size_t)BMAX * NPIX];
__device__ float d_part[(size_t)BMAX * NCELL * 9];

// =====================================================================
// Kernel 1: per-cell features (hist, HSV, Sobel, Laplacian) + gray out
// block = 64 threads (16 cols x 4 row-groups), 4 pixels per thread.
// grid = (49, B)
// =====================================================================
__global__ void __launch_bounds__(64) cell_kernel(const float* __restrict__ img,
                                                  float* __restrict__ out)
{
    const int cell = blockIdx.x;
    const int b    = blockIdx.y;
    const int cy = cell / GRID, cx = cell % GRID;
    const int tid = threadIdx.x;
    const int tx  = tid & 15;
    const int rg  = tid >> 4;          // 0..3 -> rows rg*4 .. rg*4+3

    __shared__ float sg[18][18];
    __shared__ int   shist[2][24];
    __shared__ float sred[15][2];
    __shared__ float stot[15];

    if (tid < 48) ((int*)shist)[tid] = 0;

    const float* base = img + (size_t)b * 3 * NPIX;
    const int oy = cy * 16 - 1;
    const int ox = cx * 16 - 1;
    const int gx = cx * 16 + tx;

    // load 4 pixels (rows rg*4..rg*4+3 at column tx), all channels up front
    float R[4], Gc[4], Bl[4], gray[4];
    {
        const int p0 = (cy * 16 + rg * 4) * WW + gx;
        #pragma unroll
        for (int q = 0; q < 4; q++) {
            int p = p0 + q * WW;
            R[q]  = base[p];
            Gc[q] = base[NPIX + p];
            Bl[q] = base[2 * NPIX + p];
        }
        #pragma unroll
        for (int q = 0; q < 4; q++) {
            gray[q] = 0.299f * R[q] + 0.587f * Gc[q] + 0.114f * Bl[q];
            sg[rg * 4 + q + 1][tx + 1] = gray[q];
            d_gray[(size_t)b * NPIX + p0 + q * WW] = gray[q];
        }
    }

    // halo: 68 perimeter positions of the 18x18 tile, coords clamped
    for (int i = tid; i < 68; i += 64) {
        int rr, cc;
        if (i < 18)      { rr = 0;          cc = i; }
        else if (i < 36) { rr = 17;         cc = i - 18; }
        else if (i < 52) { rr = i - 36 + 1; cc = 0; }
        else             { rr = i - 52 + 1; cc = 17; }
        int yy = min(max(oy + rr, 0), HH - 1);
        int xx = min(max(ox + cc, 0), WW - 1);
        int pp = yy * WW + xx;
        sg[rr][cc] = 0.299f * base[pp] + 0.587f * base[NPIX + pp] + 0.114f * base[2 * NPIX + pp];
    }
    __syncthreads();

    // x-direction clamp / reflect indices hoisted out of the row loop
    const int x0  = tx + 1;
    const int xm  = min(max(gx - 1, 0), WW - 1) - ox;
    const int xp  = min(max(gx + 1, 0), WW - 1) - ox;
    const int Rxm = ((gx - 1) < 0      ? 1      : (gx - 1)) - ox;
    const int Rxp = ((gx + 1) > WW - 1 ? WW - 2 : (gx + 1)) - ox;
    const int hc = tid & 1;            // histogram copy (2-way replication)

    float acc[15];
    #pragma unroll
    for (int k = 0; k < 15; k++) acc[k] = 0.0f;

    #pragma unroll
    for (int q = 0; q < 4; q++) {
        const int row = rg * 4 + q;
        const int gy  = cy * 16 + row;
        const float r = R[q], g = Gc[q], bl = Bl[q];

        // --- histogram ---
        int ir = (int)floorf(r  * 8.0f); if (ir >= 0 && ir < 8) atomicAdd(&shist[hc][ir], 1);
        int ig = (int)floorf(g  * 8.0f); if (ig >= 0 && ig < 8) atomicAdd(&shist[hc][8 + ig], 1);
        int ib = (int)floorf(bl * 8.0f); if (ib >= 0 && ib < 8) atomicAdd(&shist[hc][16 + ib], 1);

        // --- HSV (matches reference branch order exactly) ---
        float maxc = fmaxf(r, fmaxf(g, bl));
        float minc = fminf(r, fminf(g, bl));
        float vv = maxc;
        float delta = maxc - minc;
        float ss = delta / (maxc + 1e-8f);
        float dsafe = (delta == 0.0f) ? 1.0f : delta;
        float rc = (maxc - r)  / dsafe;
        float gc = (maxc - g)  / dsafe;
        float bc = (maxc - bl) / dsafe;
        float hh;
        if (maxc == r)      hh = bc - gc;
        else if (maxc == g) hh = 2.0f + rc - bc;
        else                hh = 4.0f + gc - rc;
        hh = hh / 6.0f;
        hh = hh - floorf(hh);
        hh = hh * TWO_PI_F;

        // --- Sobel (edge/clamp padding) ---
        const int y0 = row + 1;
        const int ym = min(max(gy - 1, 0), HH - 1) - oy;
        const int yp = min(max(gy + 1, 0), HH - 1) - oy;
        float gxv = 0.125f * ((sg[ym][xp] + 2.0f * sg[y0][xp] + sg[yp][xp])
                            - (sg[ym][xm] + 2.0f * sg[y0][xm] + sg[yp][xm]));
        float gyv = 0.125f * ((sg[yp][xm] + 2.0f * sg[yp][x0] + sg[yp][xp])
                            - (sg[ym][xm] + 2.0f * sg[ym][x0] + sg[ym][xp]));
        float mag = sqrtf(gxv * gxv + gyv * gyv + 1e-8f);
        float d2  = gxv * gxv + gyv * gyv;
        float ca  = (d2 > 0.0f) ? gxv * rsqrtf(d2) : 1.0f;   // cos(atan2)

        // --- Laplacian (reflect padding) ---
        const int Rym = ((gy - 1) < 0      ? 1      : (gy - 1)) - oy;
        const int Ryp = ((gy + 1) > HH - 1 ? HH - 2 : (gy + 1)) - oy;
        float nb = sg[Rym][Rxm] + sg[Rym][x0] + sg[Rym][Rxp]
                 + sg[y0][Rxm]               + sg[y0][Rxp]
                 + sg[Ryp][Rxm] + sg[Ryp][x0] + sg[Ryp][Rxp];
        float lap = 0.0625f * nb - 0.5f * sg[y0][x0];

        acc[0] += r;   acc[1] += g;   acc[2] += bl;
        acc[3] += hh;  acc[4] += ss;  acc[5] += vv;
        acc[6] += hh * hh; acc[7] += ss * ss; acc[8] += vv * vv;
        acc[9] += mag; acc[10] += mag * mag; acc[11] += ca;
        acc[12] += lap; acc[13] += lap * lap; acc[14] += fabsf(lap);
    }

    const int lane = tid & 31, w = tid >> 5;
    #pragma unroll
    for (int k = 0; k < 15; k++) {
        float x = acc[k];
        #pragma unroll
        for (int o = 16; o > 0; o >>= 1) x += __shfl_down_sync(0xffffffffu, x, o);
        if (lane == 0) sred[k][w] = x;
    }
    __syncthreads();
    if (tid < 15) stot[tid] = sred[tid][0] + sred[tid][1];
    __syncthreads();

    float* ob = out + (size_t)b * NFEAT;
    if (tid < 24) {
        int c = tid >> 3, bin = tid & 7;
        ob[3 + ((size_t)cell * 3 + c) * 8 + bin] =
            (float)(shist[0][tid] + shist[1][tid]) * (1.0f / 256.0f);
    }
    if (tid < 3) ob[1185 + cell * 3 + tid] = stot[3 + tid] * (1.0f / 256.0f);
    if (tid < 9) d_part[((size_t)b * NCELL + cell) * 9 + tid] = stot[tid];
    if (tid == 0) {
        float sm = stot[9], sq = stot[10];
        ob[1332 + cell * 4 + 0] = sm * (1.0f / 256.0f);
        ob[1332 + cell * 4 + 1] = sqrtf(fmaxf(0.0f, (sq - sm * sm * (1.0f / 256.0f)) * (1.0f / 255.0f)));
        ob[1332 + cell * 4 + 2] = sq * (1.0f / 256.0f);
        ob[1332 + cell * 4 + 3] = stot[11] * (1.0f / 256.0f);
        float lm = stot[12], lq = stot[13];
        ob[1528 + cell * 4 + 0] = lm * (1.0f / 256.0f);
        ob[1528 + cell * 4 + 1] = sqrtf(fmaxf(0.0f, (lq - lm * lm * (1.0f / 256.0f)) * (1.0f / 255.0f)));
        ob[1528 + cell * 4 + 2] = lq * (1.0f / 256.0f);
        ob[1528 + cell * 4 + 3] = stot[14] * (1.0f / 256.0f);
    }
}

// =====================================================================
// Kernel 2: fused Gabor (both separable passes entirely in smem, one
// block per image) + per-cell means + per-image finalize.
// smem: gray 112x132 | t0 132x112 | t1 132x112 | spart 14x112x2 | 9
// = ~186 KB -> 1 block/SM.
// =====================================================================
#define SG_OFF   0
#define T0_OFF   (112 * 132)
#define T1_OFF   (T0_OFF + 132 * 112)
#define SP_OFF   (T1_OFF + 132 * 112)
#define ST_OFF   (SP_OFF + 14 * 112 * 2)
#define GAB_SMEM ((ST_OFF + 16) * sizeof(float))

__global__ void __launch_bounds__(512) gabor_fused(const float* __restrict__ gk0,
                                                   const float* __restrict__ gk1,
                                                   float* __restrict__ out)
{
    extern __shared__ float sm[];
    float* sg = sm + SG_OFF;
    float* t0 = sm + T0_OFF;
    float* t1 = sm + T1_OFF;
    float* sp = sm + SP_OFF;
    float* st = sm + ST_OFF;

    const int b   = blockIdx.x;
    const int tid = threadIdx.x;

    // load gray image with 10-col zero halo on both sides (112 x 132)
    const float* gr = d_gray + (size_t)b * NPIX;
    for (int i = tid; i < 112 * 132; i += 512) {
        int r = i / 132, c = i % 132;
        int x = c - 10;
        sg[i] = (x >= 0 && x < WW) ? gr[r * WW + x] : 0.0f;
    }
    // zero the 10 halo rows top and bottom of t0/t1
    for (int i = tid; i < 20 * 112; i += 512) {
        int rr = i / 112, cc = i % 112;
        int row = (rr < 10) ? rr : rr + 112;
        t0[row * 112 + cc] = 0.0f;
        t1[row * 112 + cc] = 0.0f;
    }

    // horizontal factors = center row of the rank-1 21x21 kernels
    {
        float f0[21], f1[21];
        #pragma unroll
        for (int d = 0; d < 21; d++) {
            f0[d] = __ldg(&gk0[210 + d]);
            f1[d] = __ldg(&gk1[210 + d]);
        }
        __syncthreads();

        // horizontal pass: 112 rows x 16 x-groups of 7 outputs
        for (int g = tid; g < 112 * 16; g += 512) {
            int row = g >> 4, xg = g & 15;
            const float* basep = sg + row * 132 + xg * 7;
            float a0[7], a1[7];
            #pragma unroll
            for (int i = 0; i < 7; i++) { a0[i] = 0.0f; a1[i] = 0.0f; }
            #pragma unroll
            for (int k = 0; k < 27; k++) {
                float v = basep[k];
                #pragma unroll
                for (int i = 0; i < 7; i++) {
                    int d = k - i;
                    if (d >= 0 && d < 21) {
                        a0[i] = fmaf(f0[d], v, a0[i]);
                        a1[i] = fmaf(f1[d], v, a1[i]);
                    }
                }
            }
            int o = (row + 10) * 112 + xg * 7;
            #pragma unroll
            for (int i = 0; i < 7; i++) { t0[o + i] = a0[i]; t1[o + i] = a1[i]; }
        }
    }

    // vertical factors = center column / center element
    {
        float g0[21], g1[21];
        float inv0 = 1.0f / __ldg(&gk0[220]);
        float inv1 = 1.0f / __ldg(&gk1[220]);
        #pragma unroll
        for (int d = 0; d < 21; d++) {
            g0[d] = __ldg(&gk0[d * 21 + 10]) * inv0;
            g1[d] = __ldg(&gk1[d * 21 + 10]) * inv1;
        }
        __syncthreads();

        // vertical pass: 14 y-groups of 8 outputs x 112 cols
        for (int g = tid; g < 14 * 112; g += 512) {
            int x = g % 112, yg = g / 112;
            int yb = yg * 8;
            float a0[8], a1[8];
            #pragma unroll
            for (int j = 0; j < 8; j++) { a0[j] = 0.0f; a1[j] = 0.0f; }
            #pragma unroll
            for (int k = 0; k < 28; k++) {
                float v0 = t0[(yb + k) * 112 + x];
                float v1 = t1[(yb + k) * 112 + x];
                #pragma unroll
                for (int j = 0; j < 8; j++) {
                    int d = k - j;
                    if (d >= 0 && d < 21) {
                        a0[j] = fmaf(g0[d], v0, a0[j]);
                        a1[j] = fmaf(g1[d], v1, a1[j]);
                    }
                }
            }
            float s0v = 0.0f, s1v = 0.0f;
            #pragma unroll
            for (int j = 0; j < 8; j++) { s0v += fabsf(a0[j]); s1v += fabsf(a1[j]); }
            sp[yg * 224 + x * 2 + 0] = s0v;
            sp[yg * 224 + x * 2 + 1] = s1v;
        }
    }
    __syncthreads();

    float* ob = out + (size_t)b * NFEAT;

    // gabor per-cell means: 49 cells x 2 orientations
    if (tid < 98) {
        int orient = tid & 1, cellid = tid >> 1;
        int ccy = cellid / GRID, ccx = cellid % GRID;
        float s = 0.0f;
        #pragma unroll
        for (int dy = 0; dy < 2; dy++) {
            const float* rowp = sp + (2 * ccy + dy) * 224 + (16 * ccx) * 2 + orient;
            #pragma unroll
            for (int i = 0; i < 16; i++) s += rowp[i * 2];
        }
        ob[1724 + orient * NCELL + cellid] = s * (1.0f / 256.0f);
    }
    // per-image partial reduction (rgb sums, hsv sums, hsv sq-sums)
    if (tid >= 128 && tid < 137) {
        int t = tid - 128;
        const float* pp = d_part + (size_t)b * NCELL * 9;
        float a = 0.0f;
        for (int c = 0; c < NCELL; c++) a += pp[c * 9 + t];
        st[t] = a;
    }
    __syncthreads();
    if (tid == 0) {
        const float N = (float)NPIX;
        ob[0] = st[0] / N;
        ob[1] = st[1] / N;
        ob[2] = st[2] / N;
        #pragma unroll
        for (int k = 0; k < 3; k++) {
            float smv = st[3 + k];
            float sqv = st[6 + k];
            float var = (sqv - smv * smv / N) / (N - 1.0f);
            ob[1179 + 2 * k] = smv / N;
            ob[1180 + 2 * k] = sqrtf(fmaxf(var, 0.0f));
        }
    }
}

// =====================================================================
extern "C" void kernel_launch(void* const* d_in, const int* in_sizes, int n_in,
                              void* d_out, int out_size)
{
    const float* img = (const float*)d_in[0];
    const float* gk0 = (const float*)d_in[1];
    const float* gk1 = (const float*)d_in[2];
    float* out = (float*)d_out;

    int B = in_sizes[0] / (3 * NPIX);
    if (B > BMAX) B = BMAX;

    static int smem_set = 0;
    if (!smem_set) {
        cudaFuncSetAttribute(gabor_fused,
                             cudaFuncAttributeMaxDynamicSharedMemorySize,
                             (int)GAB_SMEM);
        smem_set = 1;
    }

    cell_kernel<<<dim3(NCELL, B), 64>>>(img, out);
    gabor_fused<<<B, 512, GAB_SMEM>>>(gk0, gk1, out);
}